// round 14
// baseline (speedup 1.0000x reference)
#include <cuda_runtime.h>
#include <cuda_fp16.h>
#include <cstdint>

#define DIMC  1024
#define NSEQ  1024
#define BATCH 4
#define NHEAD 16
#define HD    64
#define BHTOT (BATCH*NHEAD)

// ---------------- scratch (device globals; no allocation at runtime) ----------
__device__ __half g_Qh[(size_t)BHTOT*NSEQ*HD];
__device__ __half g_Kh[(size_t)BHTOT*NSEQ*HD];
__device__ __half g_Vh[(size_t)BHTOT*NSEQ*HD];

__device__ __half g_xh[(size_t)BATCH*NSEQ*DIMC];
__device__ __half g_wqh[(size_t)3*DIMC*DIMC];
__device__ __half g_wph[(size_t)DIMC*DIMC];
__device__ __half g_ath[(size_t)BATCH*NSEQ*DIMC];
__device__ __half g_erh[(size_t)NSEQ*HD];

// ---------------- helpers ------------------------------------------------------
__device__ __forceinline__ uint32_t smem_u32(const void* p) {
    uint32_t a;
    asm("{ .reg .u64 t; cvta.to.shared.u64 t, %1; cvt.u32.u64 %0, t; }"
        : "=r"(a) : "l"(p));
    return a;
}

__device__ __forceinline__ void cp_async16(uint32_t saddr, const void* gaddr) {
    asm volatile("cp.async.cg.shared.global [%0], [%1], 16;"
                 :: "r"(saddr), "l"(gaddr));
}
#define CP_COMMIT() asm volatile("cp.async.commit_group;" ::: "memory")
#define CP_WAIT(n)  asm volatile("cp.async.wait_group %0;" :: "n"(n) : "memory")

#define LDSM_X4(R0, R1, R2, R3, addr) \
    asm volatile("ldmatrix.sync.aligned.m8n8.x4.shared.b16 {%0,%1,%2,%3}, [%4];" \
                 : "=r"(R0), "=r"(R1), "=r"(R2), "=r"(R3) : "r"(addr))

#define LDSM_X4T(R0, R1, R2, R3, addr) \
    asm volatile("ldmatrix.sync.aligned.m8n8.x4.trans.shared.b16 {%0,%1,%2,%3}, [%4];" \
                 : "=r"(R0), "=r"(R1), "=r"(R2), "=r"(R3) : "r"(addr))

#define MMAH16816(d, a, b0, b1) \
    asm volatile("mma.sync.aligned.m16n8k16.row.col.f32.f16.f16.f32 " \
                 "{%0,%1,%2,%3}, {%4,%5,%6,%7}, {%8,%9}, {%0,%1,%2,%3};" \
                 : "+f"((d)[0]), "+f"((d)[1]), "+f"((d)[2]), "+f"((d)[3]) \
                 : "r"((a)[0]), "r"((a)[1]), "r"((a)[2]), "r"((a)[3]),   \
                   "r"(b0), "r"(b1))

// SW128 (Swizzle<3,4,3>) on byte offsets inside a 1024B-aligned tile
#define SW128(off) (((uint32_t)(off)) ^ ((((uint32_t)(off)) >> 3) & 0x70))

// ============================================================================
// Combined convert fp32 -> fp16: x, W_qkv, W_proj, Er (one launch).
// ============================================================================
#define NX4  1048576
#define NWQ4 786432
#define NWP4 262144
#define NER4 16384
#define NSPLIT4 (NX4 + NWQ4 + NWP4 + NER4)

__global__ void split_all(const float* __restrict__ x, const float* __restrict__ wq,
                          const float* __restrict__ wp, const float* __restrict__ er)
{
    int i = blockIdx.x * blockDim.x + threadIdx.x;
    if (i >= NSPLIT4) return;

    const float* src;
    __half* hi;
    int j;
    if (i < NX4)                    { src = x;  hi = g_xh;  j = i; }
    else if (i < NX4 + NWQ4)        { src = wq; hi = g_wqh; j = i - NX4; }
    else if (i < NX4 + NWQ4 + NWP4) { src = wp; hi = g_wph; j = i - NX4 - NWQ4; }
    else                            { src = er; hi = g_erh; j = i - NX4 - NWQ4 - NWP4; }

    float4 v = ((const float4*)src)[j];
    ((__half2*)hi)[2*j]   = __floats2half2_rn(v.x, v.y);
    ((__half2*)hi)[2*j+1] = __floats2half2_rn(v.z, v.w);
}

// ============================================================================
// HMMA fp16 single-product GEMM: C = A * B^T.
// Stage = {A 16KB, B 16KB} = 32KB for K=64; 3-stage ring (96KB); 2 CTAs/SM.
// MODE 0: QKV -> Q,K,V fp16 into g_{Q,K,V}h.   MODE 1: proj +bias fp32.
// ============================================================================
template<int MODE>
__global__ __launch_bounds__(256, 2)
void hmma_gemm(const float* __restrict__ bias, float* __restrict__ C)
{
    extern __shared__ char dynsm[];
    const uint32_t sbase = smem_u32(dynsm);

    const int tid  = threadIdx.x;
    const int wid  = tid >> 5;
    const int lane = tid & 31;
    const int wm = wid & 3;
    const int wn = wid >> 2;
    const int m0 = blockIdx.y * 128;
    const int n0 = blockIdx.x * 128;

    const __half* A = (MODE == 0) ? g_xh : g_ath;
    const __half* B = (MODE == 0) ? g_wqh : g_wph;

    float d[2][8][4];
#pragma unroll
    for (int mt = 0; mt < 2; mt++)
#pragma unroll
        for (int nt = 0; nt < 8; nt++)
#pragma unroll
            for (int r = 0; r < 4; r++) d[mt][nt][r] = 0.0f;

    auto issue_stage = [&](int s) {
        const int kin = s * 64;
        const uint32_t stbase = sbase + (uint32_t)(s % 3) * 32768u;
#pragma unroll
        for (int t = 0; t < 8; t++) {
            int c    = tid + t * 256;
            int part = c >> 10;
            int row  = (c >> 3) & 127;
            int seg  = c & 7;
            const __half* src = part ? B : A;
            int r0 = part ? n0 : m0;
            cp_async16(stbase + (uint32_t)part * 16384u
                           + SW128((uint32_t)(row * 128 + seg * 16)),
                       src + (size_t)(r0 + row) * 1024 + kin + seg * 8);
        }
    };

    issue_stage(0); CP_COMMIT();
    issue_stage(1); CP_COMMIT();

    for (int s = 0; s < 16; s++) {
        if (s == 15) { CP_WAIT(0); } else { CP_WAIT(1); }
        __syncthreads();   // stage s resident; all reads of slot (s%3) from s-3 done
        if (s + 2 < 16) { issue_stage(s + 2); CP_COMMIT(); }

        const uint32_t aB = sbase + (uint32_t)(s % 3) * 32768u;
        const uint32_t bB = aB + 16384u;

#pragma unroll
        for (int ks = 0; ks < 4; ks++) {
            const int kb = ks * 32;
            uint32_t a[2][4];
#pragma unroll
            for (int mt = 0; mt < 2; mt++) {
                int row = wm * 32 + mt * 16 + (lane & 15);
                uint32_t off = SW128((uint32_t)(row * 128 + kb + ((lane >> 4) << 4)));
                LDSM_X4(a[mt][0], a[mt][1], a[mt][2], a[mt][3], aB + off);
            }
            uint32_t bb[4][4];
#pragma unroll
            for (int bt = 0; bt < 4; bt++) {
                int row = wn * 64 + bt * 16 + (lane & 7) + (((lane >> 4) & 1) << 3);
                uint32_t bd = bB + SW128((uint32_t)(row * 128 + kb + (((lane >> 3) & 1) << 4)));
                LDSM_X4(bb[bt][0], bb[bt][1], bb[bt][2], bb[bt][3], bd);
            }
#pragma unroll
            for (int mt = 0; mt < 2; mt++)
#pragma unroll
                for (int nt = 0; nt < 8; nt++) {
                    int bt = nt >> 1, pr = (nt & 1) << 1;
                    MMAH16816(d[mt][nt], a[mt], bb[bt][pr], bb[bt][pr + 1]);
                }
        }
    }

    // ---- epilogue ----
#pragma unroll
    for (int mt = 0; mt < 2; mt++) {
        int rbase = m0 + wm * 32 + mt * 16 + (lane >> 2);
#pragma unroll
        for (int nt = 0; nt < 8; nt++) {
            int f = n0 + wn * 64 + nt * 8 + (lane & 3) * 2;
#pragma unroll
            for (int half = 0; half < 2; half++) {
                int m = rbase + half * 8;
                float2 v = make_float2(d[mt][nt][half * 2], d[mt][nt][half * 2 + 1]);
                if (MODE == 0) {
                    int b_i = m >> 10, n = m & 1023;
                    int sec = f >> 10;
                    int hh = (f >> 6) & 15, dd = f & 63;
                    size_t idx = ((size_t)(b_i * NHEAD + hh) * NSEQ + n) * HD + dd;
                    __half* dst = (sec == 0) ? g_Qh : (sec == 1) ? g_Kh : g_Vh;
                    *(__half2*)&dst[idx] = __floats2half2_rn(v.x, v.y);
                } else {
                    v.x += bias[f];
                    v.y += bias[f + 1];
                    *(float2*)&C[(size_t)m * DIMC + f] = v;
                }
            }
        }
    }
}

// ============================================================================
// Tensor-core fused causal flash attention with relative position term.
// All single-pass fp16: S = Q.K, R = Q.E, O += P.V.
// K/V double-buffered, E 4-slot ring.
// ============================================================================
#define OFF_Q    0u          // 16KB fp16
#define OFF_K    16384u      // 2 bufs x 8KB
#define OFF_V    32768u      // 2 bufs x 8KB
#define OFF_EHI  49152u      // 4 slots x 8KB
#define OFF_R    81920u      // 8 warps x 1600 floats
#define ATTN_SMEM 133120

__global__ __launch_bounds__(256)
void attn_kernel()
{
    extern __shared__ char smc[];
    const uint32_t sb = smem_u32(smc);
    const int tid  = threadIdx.x;
    const int w    = tid >> 5;
    const int lane = tid & 31;
    const int bq = 7 - (int)blockIdx.x;     // heavy blocks first
    const int bh = blockIdx.y;
    const int n0 = bq * 128;

    const size_t bho = (size_t)bh * NSEQ * HD;
    const __half* Qg = g_Qh + bho;
    const __half* Kg = g_Kh + bho;
    const __half* Vg = g_Vh + bho;

    const int base0 = NSEQ - 128 - n0;      // 64-aligned, >= 0
    const int c0 = base0 >> 6;              // first E chunk index

    // ---- load Q (128 rows fp16, 16KB) ----
#pragma unroll
    for (int t = 0; t < 4; t++) {
        int c = tid + t * 256;
        int row = c >> 3;
        int seg = c & 7;
        cp_async16(sb + OFF_Q + SW128(row * 128 + seg * 16),
                   Qg + (size_t)(n0 + row) * HD + seg * 8);
    }

    auto issueK = [&](int kt) {
        const int km0 = kt * 64;
        const uint32_t kB = OFF_K + (uint32_t)(kt & 1) * 8192u;
#pragma unroll
        for (int t = 0; t < 2; t++) {
            int c = tid + t * 256;
            int row = c >> 3;
            int seg = c & 7;
            cp_async16(sb + kB + SW128(row * 128 + seg * 16),
                       Kg + (size_t)(km0 + row) * HD + seg * 8);
        }
    };
    auto issueV = [&](int kt) {
        const int km0 = kt * 64;
        const uint32_t vB = OFF_V + (uint32_t)(kt & 1) * 8192u;
#pragma unroll
        for (int t = 0; t < 2; t++) {
            int c = tid + t * 256;
            int row = c >> 3;
            int seg = c & 7;
            cp_async16(sb + vB + SW128(row * 128 + seg * 16),
                       Vg + (size_t)(km0 + row) * HD + seg * 8);
        }
    };
    auto issueEchunk = [&](int ci) {
        const int rb = ci << 6;
        const uint32_t slot = ((uint32_t)ci & 3u) * 8192u;
#pragma unroll
        for (int t = 0; t < 2; t++) {
            int c = tid + t * 256;
            int row = c >> 3;
            int seg = c & 7;
            int r = rb + row;
            uint32_t off = OFF_EHI + slot + SW128(row * 128 + seg * 16);
            if (r < NSEQ) {
                cp_async16(sb + off, g_erh + (size_t)r * HD + seg * 8);
            } else {
                *(uint4*)(smc + off) = make_uint4(0u, 0u, 0u, 0u);
            }
        }
    };

    issueK(0); issueV(0);
    issueEchunk(c0); issueEchunk(c0 + 1); issueEchunk(c0 + 2);
    CP_COMMIT();

    float mrow[2] = {-1e30f, -1e30f};
    float lrow[2] = {0.0f, 0.0f};
    float O[8][4];
#pragma unroll
    for (int nt = 0; nt < 8; nt++)
#pragma unroll
        for (int r = 0; r < 4; r++) O[nt][r] = 0.0f;

    const int t0w = 112 - 16 * w;
    const int ktmax = 2 * bq + 1;
    const int eRow0 = base0 + t0w + (lane & 7) + (((lane >> 4) & 1) << 3);

    float* sRd = (float*)(smc + OFF_R) + w * 1600;

    for (int kt = 0; kt <= ktmax; kt++) {
        const int km0 = kt * 64;
        CP_WAIT(0);
        __syncthreads();    // K/E/V(kt) (+Q first iter) visible; prior reads done

        float S[8][4], R[10][4];
#pragma unroll
        for (int nt = 0; nt < 8; nt++)
#pragma unroll
            for (int r = 0; r < 4; r++) S[nt][r] = 0.0f;
#pragma unroll
        for (int nt = 0; nt < 10; nt++)
#pragma unroll
            for (int r = 0; r < 4; r++) R[nt][r] = 0.0f;

        const int eRowK = eRow0 + km0;
        const uint32_t kB   = sb + OFF_K + (uint32_t)(kt & 1) * 8192u;
        const uint32_t eHiB = sb + OFF_EHI;

        // ---- S = Q.K^T and R = Q.E^T (single pass each) ----
#pragma unroll
        for (int ks = 0; ks < 4; ks++) {
            const int kb = ks * 32;
            const int arow = 16 * w + (lane & 15);
            uint32_t aH[4];
            LDSM_X4(aH[0], aH[1], aH[2], aH[3],
                    sb + OFF_Q + SW128(arow * 128 + kb + ((lane >> 4) << 4)));

            uint32_t bb[5][4];
#pragma unroll
            for (int bt = 0; bt < 4; bt++) {
                int row = bt * 16 + (lane & 7) + (((lane >> 4) & 1) << 3);
                uint32_t bd = kB + SW128(row * 128 + kb + (((lane >> 3) & 1) << 4));
                LDSM_X4(bb[bt][0], bb[bt][1], bb[bt][2], bb[bt][3], bd);
            }
#pragma unroll
            for (int nt = 0; nt < 8; nt++) {
                int bt = nt >> 1, pr = (nt & 1) << 1;
                MMAH16816(S[nt], aH, bb[bt][pr], bb[bt][pr + 1]);
            }
#pragma unroll
            for (int bt = 0; bt < 5; bt++) {
                int r = eRowK + bt * 16;
                uint32_t bd = eHiB + (((uint32_t)(r >> 6) & 3u) * 8192u)
                            + SW128((r & 63) * 128 + kb + (((lane >> 3) & 1) << 4));
                LDSM_X4(bb[bt][0], bb[bt][1], bb[bt][2], bb[bt][3], bd);
            }
#pragma unroll
            for (int nt = 0; nt < 10; nt++) {
                int bt = nt >> 1, pr = (nt & 1) << 1;
                MMAH16816(R[nt], aH, bb[bt][pr], bb[bt][pr + 1]);
            }
        }

        // ---- prefetch next tile (disjoint buffers/slots; no sync needed) ----
        if (kt < ktmax) {
            issueK(kt + 1); issueV(kt + 1); issueEchunk(c0 + kt + 3);
            CP_COMMIT();
        }

        // ---- store R diagonal-shifted: (r,c) -> idx 101*r + c + 1 ----
        {
            int r0 = lane >> 2;
#pragma unroll
            for (int nt = 0; nt < 10; nt++) {
                int cA = nt * 8 + (lane & 3) * 2;
                int i0 = 101 * r0 + cA + 1;
                sRd[i0]     = R[nt][0];
                sRd[i0 + 1] = R[nt][1];
                int i1 = i0 + 101 * 8;
                sRd[i1]     = R[nt][2];
                sRd[i1 + 1] = R[nt][3];
            }
        }
        __syncwarp();

        // ---- gather rel (aligned float2 at il*100 + j0 + 16), scale, mask ----
        const bool maskt = (kt >= 2 * bq);
#pragma unroll
        for (int nt = 0; nt < 8; nt++) {
            int j0 = nt * 8 + (lane & 3) * 2;
#pragma unroll
            for (int h = 0; h < 2; h++) {
                int il = (lane >> 2) + 8 * h;
                float2 rv = *(const float2*)&sRd[il * 100 + j0 + 16];
                float s0 = (S[nt][2 * h]     + rv.x) * 0.125f;
                float s1 = (S[nt][2 * h + 1] + rv.y) * 0.125f;
                if (maskt) {
                    int ig = n0 + 16 * w + il;
                    int jg = km0 + j0;
                    if (jg > ig)     s0 = -1e30f;
                    if (jg + 1 > ig) s1 = -1e30f;
                }
                S[nt][2 * h]     = s0;
                S[nt][2 * h + 1] = s1;
            }
        }

        // ---- online softmax (rows warp-local; quad = 4 lanes per row) ----
        float alpha[2];
#pragma unroll
        for (int h = 0; h < 2; h++) {
            float v = -1e30f;
#pragma unroll
            for (int nt = 0; nt < 8; nt++)
                v = fmaxf(v, fmaxf(S[nt][2 * h], S[nt][2 * h + 1]));
            v = fmaxf(v, __shfl_xor_sync(0xffffffffu, v, 1));
            v = fmaxf(v, __shfl_xor_sync(0xffffffffu, v, 2));
            float mnew = fmaxf(mrow[h], v);
            alpha[h] = __expf(mrow[h] - mnew);
            mrow[h] = mnew;
        }
        float rsum[2] = {0.0f, 0.0f};
#pragma unroll
        for (int nt = 0; nt < 8; nt++)
#pragma unroll
            for (int h = 0; h < 2; h++) {
                float p0 = __expf(S[nt][2 * h]     - mrow[h]);
                float p1 = __expf(S[nt][2 * h + 1] - mrow[h]);
                S[nt][2 * h] = p0; S[nt][2 * h + 1] = p1;
                rsum[h] += p0 + p1;
            }
#pragma unroll
        for (int h = 0; h < 2; h++) {
            rsum[h] += __shfl_xor_sync(0xffffffffu, rsum[h], 1);
            rsum[h] += __shfl_xor_sync(0xffffffffu, rsum[h], 2);
            lrow[h] = lrow[h] * alpha[h] + rsum[h];
        }
#pragma unroll
        for (int nt = 0; nt < 8; nt++) {
            O[nt][0] *= alpha[0]; O[nt][1] *= alpha[0];
            O[nt][2] *= alpha[1]; O[nt][3] *= alpha[1];
        }

        // ---- pack P fp16 in registers (S-frag layout == A-frag layout) ----
        uint32_t PH[8][2];
#pragma unroll
        for (int nt = 0; nt < 8; nt++) {
#pragma unroll
            for (int pr = 0; pr < 2; pr++) {
                __half2 hh = __floats2half2_rn(S[nt][2 * pr], S[nt][2 * pr + 1]);
                PH[nt][pr] = *(uint32_t*)&hh;
            }
        }

        // ---- O += P.V (single pass, V via ldmatrix.trans) ----
        const uint32_t vB = sb + OFF_V + (uint32_t)(kt & 1) * 8192u;
#pragma unroll
        for (int ks = 0; ks < 4; ks++) {
            uint32_t aP[4] = {PH[2*ks][0], PH[2*ks][1], PH[2*ks+1][0], PH[2*ks+1][1]};
            int row = ks * 16 + (lane & 15);
#pragma unroll
            for (int bt = 0; bt < 4; bt++) {
                uint32_t bd = vB + SW128(row * 128 + bt * 32 + ((lane >> 4) << 4));
                uint32_t r0, r1, r2, r3;
                LDSM_X4T(r0, r1, r2, r3, bd);
                MMAH16816(O[2*bt],     aP, r0, r1);
                MMAH16816(O[2*bt + 1], aP, r2, r3);
            }
        }
    }

    // ---- epilogue: O /= l, fp16 -> g_ath[b][n][h*64+d] ----
    const int b_i = bh >> 4, hhead = bh & 15;
    float inv[2] = {1.0f / lrow[0], 1.0f / lrow[1]};
#pragma unroll
    for (int nt = 0; nt < 8; nt++) {
        int c = hhead * 64 + nt * 8 + (lane & 3) * 2;
#pragma unroll
        for (int h = 0; h < 2; h++) {
            int n = n0 + 16 * w + (lane >> 2) + 8 * h;
            float o0 = O[nt][2 * h] * inv[h];
            float o1 = O[nt][2 * h + 1] * inv[h];
            size_t idx = ((size_t)b_i * NSEQ + n) * DIMC + c;
            *(__half2*)&g_ath[idx] = __floats2half2_rn(o0, o1);
        }
    }
}

// ============================================================================
extern "C" void kernel_launch(void* const* d_in, const int* in_sizes, int n_in,
                              void* d_out, int out_size)
{
    const float* x      = (const float*)d_in[0];
    const float* W_qkv  = (const float*)d_in[1];
    const float* W_proj = (const float*)d_in[2];
    const float* b_proj = (const float*)d_in[3];
    const float* Er     = (const float*)d_in[4];
    float* out = (float*)d_out;

    // 0) fp32 -> fp16 conversions (single launch)
    split_all<<<(NSPLIT4 + 255) / 256, 256>>>(x, W_qkv, W_proj, Er);

    // 1) QKV via fp16 HMMA: M=4096, N=3072 (3-stage x 32KB = 96 KB)
    const int gsmem = 3 * 32768;
    cudaFuncSetAttribute(hmma_gemm<0>,
                         cudaFuncAttributeMaxDynamicSharedMemorySize, gsmem);
    cudaFuncSetAttribute(hmma_gemm<1>,
                         cudaFuncAttributeMaxDynamicSharedMemorySize, gsmem);
    hmma_gemm<0><<<dim3(24, 32), 256, gsmem>>>(nullptr, nullptr);

    // 2) tensor-core fused attention (8 q-blocks x 64 bh)
    cudaFuncSetAttribute(attn_kernel,
                         cudaFuncAttributeMaxDynamicSharedMemorySize, ATTN_SMEM);
    attn_kernel<<<dim3(8, 64), 256, ATTN_SMEM>>>();

    // 3) proj via fp16 HMMA: M=4096, N=1024, +bias
    hmma_gemm<1><<<dim3(8, 32), 256, gsmem>>>(b_proj, out);
}

// round 15
// speedup vs baseline: 1.4518x; 1.4518x over previous
#include <cuda_runtime.h>
#include <cuda_fp16.h>
#include <cstdint>

#define DIMC  1024
#define NSEQ  1024
#define BATCH 4
#define NHEAD 16
#define HD    64
#define BHTOT (BATCH*NHEAD)

// ---------------- scratch (device globals; no allocation at runtime) ----------
__device__ __half g_Qh[(size_t)BHTOT*NSEQ*HD];
__device__ __half g_Kh[(size_t)BHTOT*NSEQ*HD];
__device__ __half g_Vh[(size_t)BHTOT*NSEQ*HD];   // fp16 split
__device__ __half g_Vl[(size_t)BHTOT*NSEQ*HD];

__device__ __half g_xh[(size_t)BATCH*NSEQ*DIMC];
__device__ __half g_wqh[(size_t)3*DIMC*DIMC];
__device__ __half g_wph[(size_t)DIMC*DIMC];
__device__ __half g_ath[(size_t)BATCH*NSEQ*DIMC];
__device__ __half g_erh[(size_t)NSEQ*HD];

// ---------------- helpers ------------------------------------------------------
__device__ __forceinline__ uint32_t smem_u32(const void* p) {
    uint32_t a;
    asm("{ .reg .u64 t; cvta.to.shared.u64 t, %1; cvt.u32.u64 %0, t; }"
        : "=r"(a) : "l"(p));
    return a;
}

__device__ __forceinline__ void cp_async16(uint32_t saddr, const void* gaddr) {
    asm volatile("cp.async.cg.shared.global [%0], [%1], 16;"
                 :: "r"(saddr), "l"(gaddr));
}
#define CP_COMMIT() asm volatile("cp.async.commit_group;" ::: "memory")
#define CP_WAIT(n)  asm volatile("cp.async.wait_group %0;" :: "n"(n) : "memory")

#define LDSM_X4(R0, R1, R2, R3, addr) \
    asm volatile("ldmatrix.sync.aligned.m8n8.x4.shared.b16 {%0,%1,%2,%3}, [%4];" \
                 : "=r"(R0), "=r"(R1), "=r"(R2), "=r"(R3) : "r"(addr))

#define LDSM_X4T(R0, R1, R2, R3, addr) \
    asm volatile("ldmatrix.sync.aligned.m8n8.x4.trans.shared.b16 {%0,%1,%2,%3}, [%4];" \
                 : "=r"(R0), "=r"(R1), "=r"(R2), "=r"(R3) : "r"(addr))

#define MMAH16816(d, a, b0, b1) \
    asm volatile("mma.sync.aligned.m16n8k16.row.col.f32.f16.f16.f32 " \
                 "{%0,%1,%2,%3}, {%4,%5,%6,%7}, {%8,%9}, {%0,%1,%2,%3};" \
                 : "+f"((d)[0]), "+f"((d)[1]), "+f"((d)[2]), "+f"((d)[3]) \
                 : "r"((a)[0]), "r"((a)[1]), "r"((a)[2]), "r"((a)[3]),   \
                   "r"(b0), "r"(b1))

// SW128 (Swizzle<3,4,3>) on byte offsets inside a 1024B-aligned tile
#define SW128(off) (((uint32_t)(off)) ^ ((((uint32_t)(off)) >> 3) & 0x70))

// ============================================================================
// Combined convert fp32 -> fp16: x, W_qkv, W_proj, Er (one launch).
// ============================================================================
#define NX4  1048576
#define NWQ4 786432
#define NWP4 262144
#define NER4 16384
#define NSPLIT4 (NX4 + NWQ4 + NWP4 + NER4)

__global__ void split_all(const float* __restrict__ x, const float* __restrict__ wq,
                          const float* __restrict__ wp, const float* __restrict__ er)
{
    int i = blockIdx.x * blockDim.x + threadIdx.x;
    if (i >= NSPLIT4) return;

    const float* src;
    __half* hi;
    int j;
    if (i < NX4)                    { src = x;  hi = g_xh;  j = i; }
    else if (i < NX4 + NWQ4)        { src = wq; hi = g_wqh; j = i - NX4; }
    else if (i < NX4 + NWQ4 + NWP4) { src = wp; hi = g_wph; j = i - NX4 - NWQ4; }
    else                            { src = er; hi = g_erh; j = i - NX4 - NWQ4 - NWP4; }

    float4 v = ((const float4*)src)[j];
    ((__half2*)hi)[2*j]   = __floats2half2_rn(v.x, v.y);
    ((__half2*)hi)[2*j+1] = __floats2half2_rn(v.z, v.w);
}

// ============================================================================
// HMMA fp16 single-product GEMM: C = A * B^T.
// Stage = {A 16KB, B 16KB} = 32KB for K=64; 3-stage ring (96KB); 2 CTAs/SM.
// MODE 0: QKV -> Q,K fp16 single; V fp16 hi/lo.   MODE 1: proj +bias fp32.
// ============================================================================
template<int MODE>
__global__ __launch_bounds__(256, 2)
void hmma_gemm(const float* __restrict__ bias, float* __restrict__ C)
{
    extern __shared__ char dynsm[];
    const uint32_t sbase = smem_u32(dynsm);

    const int tid  = threadIdx.x;
    const int wid  = tid >> 5;
    const int lane = tid & 31;
    const int wm = wid & 3;
    const int wn = wid >> 2;
    const int m0 = blockIdx.y * 128;
    const int n0 = blockIdx.x * 128;

    const __half* A = (MODE == 0) ? g_xh : g_ath;
    const __half* B = (MODE == 0) ? g_wqh : g_wph;

    float d[2][8][4];
#pragma unroll
    for (int mt = 0; mt < 2; mt++)
#pragma unroll
        for (int nt = 0; nt < 8; nt++)
#pragma unroll
            for (int r = 0; r < 4; r++) d[mt][nt][r] = 0.0f;

    auto issue_stage = [&](int s) {
        const int kin = s * 64;
        const uint32_t stbase = sbase + (uint32_t)(s % 3) * 32768u;
#pragma unroll
        for (int t = 0; t < 8; t++) {
            int c    = tid + t * 256;
            int part = c >> 10;
            int row  = (c >> 3) & 127;
            int seg  = c & 7;
            const __half* src = part ? B : A;
            int r0 = part ? n0 : m0;
            cp_async16(stbase + (uint32_t)part * 16384u
                           + SW128((uint32_t)(row * 128 + seg * 16)),
                       src + (size_t)(r0 + row) * 1024 + kin + seg * 8);
        }
    };

    issue_stage(0); CP_COMMIT();
    issue_stage(1); CP_COMMIT();

    for (int s = 0; s < 16; s++) {
        if (s == 15) { CP_WAIT(0); } else { CP_WAIT(1); }
        __syncthreads();   // stage s resident; all reads of slot (s%3) from s-3 done
        if (s + 2 < 16) { issue_stage(s + 2); CP_COMMIT(); }

        const uint32_t aB = sbase + (uint32_t)(s % 3) * 32768u;
        const uint32_t bB = aB + 16384u;

#pragma unroll
        for (int ks = 0; ks < 4; ks++) {
            const int kb = ks * 32;
            uint32_t a[2][4];
#pragma unroll
            for (int mt = 0; mt < 2; mt++) {
                int row = wm * 32 + mt * 16 + (lane & 15);
                uint32_t off = SW128((uint32_t)(row * 128 + kb + ((lane >> 4) << 4)));
                LDSM_X4(a[mt][0], a[mt][1], a[mt][2], a[mt][3], aB + off);
            }
            uint32_t bb[4][4];
#pragma unroll
            for (int bt = 0; bt < 4; bt++) {
                int row = wn * 64 + bt * 16 + (lane & 7) + (((lane >> 4) & 1) << 3);
                uint32_t bd = bB + SW128((uint32_t)(row * 128 + kb + (((lane >> 3) & 1) << 4)));
                LDSM_X4(bb[bt][0], bb[bt][1], bb[bt][2], bb[bt][3], bd);
            }
#pragma unroll
            for (int mt = 0; mt < 2; mt++)
#pragma unroll
                for (int nt = 0; nt < 8; nt++) {
                    int bt = nt >> 1, pr = (nt & 1) << 1;
                    MMAH16816(d[mt][nt], a[mt], bb[bt][pr], bb[bt][pr + 1]);
                }
        }
    }

    // ---- epilogue ----
#pragma unroll
    for (int mt = 0; mt < 2; mt++) {
        int rbase = m0 + wm * 32 + mt * 16 + (lane >> 2);
#pragma unroll
        for (int nt = 0; nt < 8; nt++) {
            int f = n0 + wn * 64 + nt * 8 + (lane & 3) * 2;
#pragma unroll
            for (int half = 0; half < 2; half++) {
                int m = rbase + half * 8;
                float2 v = make_float2(d[mt][nt][half * 2], d[mt][nt][half * 2 + 1]);
                if (MODE == 0) {
                    int b_i = m >> 10, n = m & 1023;
                    int sec = f >> 10;
                    int hh = (f >> 6) & 15, dd = f & 63;
                    size_t idx = ((size_t)(b_i * NHEAD + hh) * NSEQ + n) * HD + dd;
                    if (sec == 2) {
                        __half h0 = __float2half_rn(v.x);
                        __half h1 = __float2half_rn(v.y);
                        __half l0 = __float2half_rn(v.x - __half2float(h0));
                        __half l1 = __float2half_rn(v.y - __half2float(h1));
                        *(__half2*)&g_Vh[idx] = __halves2half2(h0, h1);
                        *(__half2*)&g_Vl[idx] = __halves2half2(l0, l1);
                    } else {
                        __half* dst = (sec == 0) ? g_Qh : g_Kh;
                        *(__half2*)&dst[idx] = __floats2half2_rn(v.x, v.y);
                    }
                } else {
                    v.x += bias[f];
                    v.y += bias[f + 1];
                    *(float2*)&C[(size_t)m * DIMC + f] = v;
                }
            }
        }
    }
}

// ============================================================================
// Tensor-core fused causal flash attention with relative position term.
// fp16: S = Qh.Kh (1 pass), R = Qh.Ehi (1 pass), PV = Ph.(Vh + Vl) (2 passes).
// K/V double-buffered, E fp16 hi 4-slot ring.   (R13 configuration)
// ============================================================================
#define OFF_Q    0u          // 16KB fp16
#define OFF_K    16384u      // 2 bufs x 8KB fp16
#define OFF_V    32768u      // 2 bufs x (8KB hi + 8KB lo) fp16
#define OFF_EHI  65536u      // 4 slots x 8KB fp16
#define OFF_R    98304u      // 8 warps x 1600 floats
#define ATTN_SMEM 149504

__global__ __launch_bounds__(256)
void attn_kernel()
{
    extern __shared__ char smc[];
    const uint32_t sb = smem_u32(smc);
    const int tid  = threadIdx.x;
    const int w    = tid >> 5;
    const int lane = tid & 31;
    const int bq = 7 - (int)blockIdx.x;     // heavy blocks first
    const int bh = blockIdx.y;
    const int n0 = bq * 128;

    const size_t bho = (size_t)bh * NSEQ * HD;
    const __half* Qg = g_Qh + bho;
    const __half* Kg = g_Kh + bho;
    const __half* Vhg = g_Vh + bho;
    const __half* Vlg = g_Vl + bho;

    const int base0 = NSEQ - 128 - n0;      // 64-aligned, >= 0
    const int c0 = base0 >> 6;              // first E chunk index

    // ---- load Q (128 rows fp16, 16KB) ----
#pragma unroll
    for (int t = 0; t < 4; t++) {
        int c = tid + t * 256;
        int row = c >> 3;
        int seg = c & 7;
        cp_async16(sb + OFF_Q + SW128(row * 128 + seg * 16),
                   Qg + (size_t)(n0 + row) * HD + seg * 8);
    }

    auto issueK = [&](int kt) {
        const int km0 = kt * 64;
        const uint32_t kB = OFF_K + (uint32_t)(kt & 1) * 8192u;
#pragma unroll
        for (int t = 0; t < 2; t++) {
            int c = tid + t * 256;
            int row = c >> 3;
            int seg = c & 7;
            cp_async16(sb + kB + SW128(row * 128 + seg * 16),
                       Kg + (size_t)(km0 + row) * HD + seg * 8);
        }
    };
    auto issueV = [&](int kt) {
        const int km0 = kt * 64;
        const uint32_t vB = OFF_V + (uint32_t)(kt & 1) * 16384u;
#pragma unroll
        for (int t = 0; t < 4; t++) {
            int c = tid + t * 256;
            int buf = c >> 9;
            int row = (c >> 3) & 63;
            int seg = c & 7;
            const __half* src = buf ? Vlg : Vhg;
            cp_async16(sb + vB + (buf ? 8192u : 0u) + SW128(row * 128 + seg * 16),
                       src + (size_t)(km0 + row) * HD + seg * 8);
        }
    };
    auto issueEchunk = [&](int ci) {
        const int rb = ci << 6;
        const uint32_t slot = ((uint32_t)ci & 3u) * 8192u;
#pragma unroll
        for (int t = 0; t < 2; t++) {
            int c = tid + t * 256;
            int row = c >> 3;
            int seg = c & 7;
            int r = rb + row;
            uint32_t off = OFF_EHI + slot + SW128(row * 128 + seg * 16);
            if (r < NSEQ) {
                cp_async16(sb + off, g_erh + (size_t)r * HD + seg * 8);
            } else {
                *(uint4*)(smc + off) = make_uint4(0u, 0u, 0u, 0u);
            }
        }
    };

    issueK(0); issueV(0);
    issueEchunk(c0); issueEchunk(c0 + 1); issueEchunk(c0 + 2);
    CP_COMMIT();

    float mrow[2] = {-1e30f, -1e30f};
    float lrow[2] = {0.0f, 0.0f};
    float O[8][4];
#pragma unroll
    for (int nt = 0; nt < 8; nt++)
#pragma unroll
        for (int r = 0; r < 4; r++) O[nt][r] = 0.0f;

    const int t0w = 112 - 16 * w;
    const int ktmax = 2 * bq + 1;
    const int eRow0 = base0 + t0w + (lane & 7) + (((lane >> 4) & 1) << 3);

    float* sRd = (float*)(smc + OFF_R) + w * 1600;

    for (int kt = 0; kt <= ktmax; kt++) {
        const int km0 = kt * 64;
        CP_WAIT(0);
        __syncthreads();    // K/E/V(kt) (+Q first iter) visible; prior reads done

        float S[8][4], R[10][4];
#pragma unroll
        for (int nt = 0; nt < 8; nt++)
#pragma unroll
            for (int r = 0; r < 4; r++) S[nt][r] = 0.0f;
#pragma unroll
        for (int nt = 0; nt < 10; nt++)
#pragma unroll
            for (int r = 0; r < 4; r++) R[nt][r] = 0.0f;

        const int eRowK = eRow0 + km0;
        const uint32_t kB   = sb + OFF_K + (uint32_t)(kt & 1) * 8192u;
        const uint32_t eHiB = sb + OFF_EHI;

        // ---- S = Qh.Kh^T and R = Qh.Ehi^T (single pass each) ----
#pragma unroll
        for (int ks = 0; ks < 4; ks++) {
            const int kb = ks * 32;
            const int arow = 16 * w + (lane & 15);
            uint32_t aH[4];
            LDSM_X4(aH[0], aH[1], aH[2], aH[3],
                    sb + OFF_Q + SW128(arow * 128 + kb + ((lane >> 4) << 4)));

            uint32_t bb[5][4];
#pragma unroll
            for (int bt = 0; bt < 4; bt++) {
                int row = bt * 16 + (lane & 7) + (((lane >> 4) & 1) << 3);
                uint32_t bd = kB + SW128(row * 128 + kb + (((lane >> 3) & 1) << 4));
                LDSM_X4(bb[bt][0], bb[bt][1], bb[bt][2], bb[bt][3], bd);
            }
#pragma unroll
            for (int nt = 0; nt < 8; nt++) {
                int bt = nt >> 1, pr = (nt & 1) << 1;
                MMAH16816(S[nt], aH, bb[bt][pr], bb[bt][pr + 1]);
            }
#pragma unroll
            for (int bt = 0; bt < 5; bt++) {
                int r = eRowK + bt * 16;
                uint32_t bd = eHiB + (((uint32_t)(r >> 6) & 3u) * 8192u)
                            + SW128((r & 63) * 128 + kb + (((lane >> 3) & 1) << 4));
                LDSM_X4(bb[bt][0], bb[bt][1], bb[bt][2], bb[bt][3], bd);
            }
#pragma unroll
            for (int nt = 0; nt < 10; nt++) {
                int bt = nt >> 1, pr = (nt & 1) << 1;
                MMAH16816(R[nt], aH, bb[bt][pr], bb[bt][pr + 1]);
            }
        }

        // ---- prefetch next tile (disjoint buffers/slots; no sync needed) ----
        if (kt < ktmax) {
            issueK(kt + 1); issueV(kt + 1); issueEchunk(c0 + kt + 3);
            CP_COMMIT();
        }

        // ---- store R diagonal-shifted: (r,c) -> idx 101*r + c + 1 ----
        {
            int r0 = lane >> 2;
#pragma unroll
            for (int nt = 0; nt < 10; nt++) {
                int cA = nt * 8 + (lane & 3) * 2;
                int i0 = 101 * r0 + cA + 1;
                sRd[i0]     = R[nt][0];
                sRd[i0 + 1] = R[nt][1];
                int i1 = i0 + 101 * 8;
                sRd[i1]     = R[nt][2];
                sRd[i1 + 1] = R[nt][3];
            }
        }
        __syncwarp();

        // ---- gather rel (aligned float2 at il*100 + j0 + 16), scale, mask ----
        const bool maskt = (kt >= 2 * bq);
#pragma unroll
        for (int nt = 0; nt < 8; nt++) {
            int j0 = nt * 8 + (lane & 3) * 2;
#pragma unroll
            for (int h = 0; h < 2; h++) {
                int il = (lane >> 2) + 8 * h;
                float2 rv = *(const float2*)&sRd[il * 100 + j0 + 16];
                float s0 = (S[nt][2 * h]     + rv.x) * 0.125f;
                float s1 = (S[nt][2 * h + 1] + rv.y) * 0.125f;
                if (maskt) {
                    int ig = n0 + 16 * w + il;
                    int jg = km0 + j0;
                    if (jg > ig)     s0 = -1e30f;
                    if (jg + 1 > ig) s1 = -1e30f;
                }
                S[nt][2 * h]     = s0;
                S[nt][2 * h + 1] = s1;
            }
        }

        // ---- online softmax (rows warp-local; quad = 4 lanes per row) ----
        float alpha[2];
#pragma unroll
        for (int h = 0; h < 2; h++) {
            float v = -1e30f;
#pragma unroll
            for (int nt = 0; nt < 8; nt++)
                v = fmaxf(v, fmaxf(S[nt][2 * h], S[nt][2 * h + 1]));
            v = fmaxf(v, __shfl_xor_sync(0xffffffffu, v, 1));
            v = fmaxf(v, __shfl_xor_sync(0xffffffffu, v, 2));
            float mnew = fmaxf(mrow[h], v);
            alpha[h] = __expf(mrow[h] - mnew);
            mrow[h] = mnew;
        }
        float rsum[2] = {0.0f, 0.0f};
#pragma unroll
        for (int nt = 0; nt < 8; nt++)
#pragma unroll
            for (int h = 0; h < 2; h++) {
                float p0 = __expf(S[nt][2 * h]     - mrow[h]);
                float p1 = __expf(S[nt][2 * h + 1] - mrow[h]);
                S[nt][2 * h] = p0; S[nt][2 * h + 1] = p1;
                rsum[h] += p0 + p1;
            }
#pragma unroll
        for (int h = 0; h < 2; h++) {
            rsum[h] += __shfl_xor_sync(0xffffffffu, rsum[h], 1);
            rsum[h] += __shfl_xor_sync(0xffffffffu, rsum[h], 2);
            lrow[h] = lrow[h] * alpha[h] + rsum[h];
        }
#pragma unroll
        for (int nt = 0; nt < 8; nt++) {
            O[nt][0] *= alpha[0]; O[nt][1] *= alpha[0];
            O[nt][2] *= alpha[1]; O[nt][3] *= alpha[1];
        }

        // ---- pack P single fp16 in registers (S-frag layout == A-frag) ----
        uint32_t PH[8][2];
#pragma unroll
        for (int nt = 0; nt < 8; nt++) {
#pragma unroll
            for (int pr = 0; pr < 2; pr++) {
                __half2 hh = __floats2half2_rn(S[nt][2 * pr], S[nt][2 * pr + 1]);
                PH[nt][pr] = *(uint32_t*)&hh;
            }
        }

        // ---- O += P.(Vh + Vl)  (fp16, 2 passes) ----
        const uint32_t vHiB = sb + OFF_V + (uint32_t)(kt & 1) * 16384u;
        const uint32_t vLoB = vHiB + 8192u;
#pragma unroll
        for (int ks = 0; ks < 4; ks++) {
            uint32_t aP[4] = {PH[2*ks][0], PH[2*ks][1], PH[2*ks+1][0], PH[2*ks+1][1]};
            int row = ks * 16 + (lane & 15);
#pragma unroll
            for (int bt = 0; bt < 4; bt++) {
                uint32_t bd = vHiB + SW128(row * 128 + bt * 32 + ((lane >> 4) << 4));
                uint32_t r0, r1, r2, r3;
                LDSM_X4T(r0, r1, r2, r3, bd);
                MMAH16816(O[2*bt],     aP, r0, r1);
                MMAH16816(O[2*bt + 1], aP, r2, r3);
            }
#pragma unroll
            for (int bt = 0; bt < 4; bt++) {
                uint32_t bd = vLoB + SW128(row * 128 + bt * 32 + ((lane >> 4) << 4));
                uint32_t r0, r1, r2, r3;
                LDSM_X4T(r0, r1, r2, r3, bd);
                MMAH16816(O[2*bt],     aP, r0, r1);
                MMAH16816(O[2*bt + 1], aP, r2, r3);
            }
        }
    }

    // ---- epilogue: O /= l, fp16 -> g_ath[b][n][h*64+d] ----
    const int b_i = bh >> 4, hhead = bh & 15;
    float inv[2] = {1.0f / lrow[0], 1.0f / lrow[1]};
#pragma unroll
    for (int nt = 0; nt < 8; nt++) {
        int c = hhead * 64 + nt * 8 + (lane & 3) * 2;
#pragma unroll
        for (int h = 0; h < 2; h++) {
            int n = n0 + 16 * w + (lane >> 2) + 8 * h;
            float o0 = O[nt][2 * h] * inv[h];
            float o1 = O[nt][2 * h + 1] * inv[h];
            size_t idx = ((size_t)b_i * NSEQ + n) * DIMC + c;
            *(__half2*)&g_ath[idx] = __floats2half2_rn(o0, o1);
        }
    }
}

// ============================================================================
extern "C" void kernel_launch(void* const* d_in, const int* in_sizes, int n_in,
                              void* d_out, int out_size)
{
    const float* x      = (const float*)d_in[0];
    const float* W_qkv  = (const float*)d_in[1];
    const float* W_proj = (const float*)d_in[2];
    const float* b_proj = (const float*)d_in[3];
    const float* Er     = (const float*)d_in[4];
    float* out = (float*)d_out;

    // 0) fp32 -> fp16 conversions (single launch)
    split_all<<<(NSPLIT4 + 255) / 256, 256>>>(x, W_qkv, W_proj, Er);

    // 1) QKV via fp16 HMMA: M=4096, N=3072 (3-stage x 32KB = 96 KB)
    const int gsmem = 3 * 32768;
    cudaFuncSetAttribute(hmma_gemm<0>,
                         cudaFuncAttributeMaxDynamicSharedMemorySize, gsmem);
    cudaFuncSetAttribute(hmma_gemm<1>,
                         cudaFuncAttributeMaxDynamicSharedMemorySize, gsmem);
    hmma_gemm<0><<<dim3(24, 32), 256, gsmem>>>(nullptr, nullptr);

    // 2) tensor-core fused attention (8 q-blocks x 64 bh)
    cudaFuncSetAttribute(attn_kernel,
                         cudaFuncAttributeMaxDynamicSharedMemorySize, ATTN_SMEM);
    attn_kernel<<<dim3(8, 64), 256, ATTN_SMEM>>>();

    // 3) proj via fp16 HMMA: M=4096, N=1024, +bias
    hmma_gemm<1><<<dim3(8, 32), 256, gsmem>>>(b_proj, out);
}

// round 16
// speedup vs baseline: 1.5214x; 1.0480x over previous
#include <cuda_runtime.h>
#include <cuda_fp16.h>
#include <cstdint>

#define DIMC  1024
#define NSEQ  1024
#define BATCH 4
#define NHEAD 16
#define HD    64
#define BHTOT (BATCH*NHEAD)

// ---------------- scratch (device globals; no allocation at runtime) ----------
__device__ __half g_Qh[(size_t)BHTOT*NSEQ*HD];
__device__ __half g_Kh[(size_t)BHTOT*NSEQ*HD];
__device__ __half g_Vh[(size_t)BHTOT*NSEQ*HD];

__device__ __half g_xh[(size_t)BATCH*NSEQ*DIMC];
__device__ __half g_wqh[(size_t)3*DIMC*DIMC];
__device__ __half g_wph[(size_t)DIMC*DIMC];
__device__ __half g_ath[(size_t)BATCH*NSEQ*DIMC];
__device__ __half g_erh[(size_t)NSEQ*HD];

// ---------------- helpers ------------------------------------------------------
__device__ __forceinline__ uint32_t smem_u32(const void* p) {
    uint32_t a;
    asm("{ .reg .u64 t; cvta.to.shared.u64 t, %1; cvt.u32.u64 %0, t; }"
        : "=r"(a) : "l"(p));
    return a;
}

__device__ __forceinline__ void cp_async16(uint32_t saddr, const void* gaddr) {
    asm volatile("cp.async.cg.shared.global [%0], [%1], 16;"
                 :: "r"(saddr), "l"(gaddr));
}
#define CP_COMMIT() asm volatile("cp.async.commit_group;" ::: "memory")
#define CP_WAIT(n)  asm volatile("cp.async.wait_group %0;" :: "n"(n) : "memory")

#define LDSM_X4(R0, R1, R2, R3, addr) \
    asm volatile("ldmatrix.sync.aligned.m8n8.x4.shared.b16 {%0,%1,%2,%3}, [%4];" \
                 : "=r"(R0), "=r"(R1), "=r"(R2), "=r"(R3) : "r"(addr))

#define LDSM_X4T(R0, R1, R2, R3, addr) \
    asm volatile("ldmatrix.sync.aligned.m8n8.x4.trans.shared.b16 {%0,%1,%2,%3}, [%4];" \
                 : "=r"(R0), "=r"(R1), "=r"(R2), "=r"(R3) : "r"(addr))

#define MMAH16816(d, a, b0, b1) \
    asm volatile("mma.sync.aligned.m16n8k16.row.col.f32.f16.f16.f32 " \
                 "{%0,%1,%2,%3}, {%4,%5,%6,%7}, {%8,%9}, {%0,%1,%2,%3};" \
                 : "+f"((d)[0]), "+f"((d)[1]), "+f"((d)[2]), "+f"((d)[3]) \
                 : "r"((a)[0]), "r"((a)[1]), "r"((a)[2]), "r"((a)[3]),   \
                   "r"(b0), "r"(b1))

// SW128 (Swizzle<3,4,3>) on byte offsets inside a 1024B-aligned tile
#define SW128(off) (((uint32_t)(off)) ^ ((((uint32_t)(off)) >> 3) & 0x70))

// ============================================================================
// Combined convert fp32 -> fp16: x, W_qkv, W_proj, Er (one launch).
// ============================================================================
#define NX4  1048576
#define NWQ4 786432
#define NWP4 262144
#define NER4 16384
#define NSPLIT4 (NX4 + NWQ4 + NWP4 + NER4)

__global__ void split_all(const float* __restrict__ x, const float* __restrict__ wq,
                          const float* __restrict__ wp, const float* __restrict__ er)
{
    int i = blockIdx.x * blockDim.x + threadIdx.x;
    if (i >= NSPLIT4) return;

    const float* src;
    __half* hi;
    int j;
    if (i < NX4)                    { src = x;  hi = g_xh;  j = i; }
    else if (i < NX4 + NWQ4)        { src = wq; hi = g_wqh; j = i - NX4; }
    else if (i < NX4 + NWQ4 + NWP4) { src = wp; hi = g_wph; j = i - NX4 - NWQ4; }
    else                            { src = er; hi = g_erh; j = i - NX4 - NWQ4 - NWP4; }

    float4 v = ((const float4*)src)[j];
    ((__half2*)hi)[2*j]   = __floats2half2_rn(v.x, v.y);
    ((__half2*)hi)[2*j+1] = __floats2half2_rn(v.z, v.w);
}

// ============================================================================
// HMMA fp16 single-product GEMM: C = A * B^T.   (unchanged from R15)
// Stage = {A 16KB, B 16KB} = 32KB for K=64; 3-stage ring (96KB); 2 CTAs/SM.
// MODE 0: QKV -> Q,K,V fp16.   MODE 1: proj +bias fp32.
// ============================================================================
template<int MODE>
__global__ __launch_bounds__(256, 2)
void hmma_gemm(const float* __restrict__ bias, float* __restrict__ C)
{
    extern __shared__ char dynsm[];
    const uint32_t sbase = smem_u32(dynsm);

    const int tid  = threadIdx.x;
    const int wid  = tid >> 5;
    const int lane = tid & 31;
    const int wm = wid & 3;
    const int wn = wid >> 2;
    const int m0 = blockIdx.y * 128;
    const int n0 = blockIdx.x * 128;

    const __half* A = (MODE == 0) ? g_xh : g_ath;
    const __half* B = (MODE == 0) ? g_wqh : g_wph;

    float d[2][8][4];
#pragma unroll
    for (int mt = 0; mt < 2; mt++)
#pragma unroll
        for (int nt = 0; nt < 8; nt++)
#pragma unroll
            for (int r = 0; r < 4; r++) d[mt][nt][r] = 0.0f;

    auto issue_stage = [&](int s) {
        const int kin = s * 64;
        const uint32_t stbase = sbase + (uint32_t)(s % 3) * 32768u;
#pragma unroll
        for (int t = 0; t < 8; t++) {
            int c    = tid + t * 256;
            int part = c >> 10;
            int row  = (c >> 3) & 127;
            int seg  = c & 7;
            const __half* src = part ? B : A;
            int r0 = part ? n0 : m0;
            cp_async16(stbase + (uint32_t)part * 16384u
                           + SW128((uint32_t)(row * 128 + seg * 16)),
                       src + (size_t)(r0 + row) * 1024 + kin + seg * 8);
        }
    };

    issue_stage(0); CP_COMMIT();
    issue_stage(1); CP_COMMIT();

    for (int s = 0; s < 16; s++) {
        if (s == 15) { CP_WAIT(0); } else { CP_WAIT(1); }
        __syncthreads();
        if (s + 2 < 16) { issue_stage(s + 2); CP_COMMIT(); }

        const uint32_t aB = sbase + (uint32_t)(s % 3) * 32768u;
        const uint32_t bB = aB + 16384u;

#pragma unroll
        for (int ks = 0; ks < 4; ks++) {
            const int kb = ks * 32;
            uint32_t a[2][4];
#pragma unroll
            for (int mt = 0; mt < 2; mt++) {
                int row = wm * 32 + mt * 16 + (lane & 15);
                uint32_t off = SW128((uint32_t)(row * 128 + kb + ((lane >> 4) << 4)));
                LDSM_X4(a[mt][0], a[mt][1], a[mt][2], a[mt][3], aB + off);
            }
            uint32_t bb[4][4];
#pragma unroll
            for (int bt = 0; bt < 4; bt++) {
                int row = wn * 64 + bt * 16 + (lane & 7) + (((lane >> 4) & 1) << 3);
                uint32_t bd = bB + SW128((uint32_t)(row * 128 + kb + (((lane >> 3) & 1) << 4)));
                LDSM_X4(bb[bt][0], bb[bt][1], bb[bt][2], bb[bt][3], bd);
            }
#pragma unroll
            for (int mt = 0; mt < 2; mt++)
#pragma unroll
                for (int nt = 0; nt < 8; nt++) {
                    int bt = nt >> 1, pr = (nt & 1) << 1;
                    MMAH16816(d[mt][nt], a[mt], bb[bt][pr], bb[bt][pr + 1]);
                }
        }
    }

    // ---- epilogue ----
#pragma unroll
    for (int mt = 0; mt < 2; mt++) {
        int rbase = m0 + wm * 32 + mt * 16 + (lane >> 2);
#pragma unroll
        for (int nt = 0; nt < 8; nt++) {
            int f = n0 + wn * 64 + nt * 8 + (lane & 3) * 2;
#pragma unroll
            for (int half = 0; half < 2; half++) {
                int m = rbase + half * 8;
                float2 v = make_float2(d[mt][nt][half * 2], d[mt][nt][half * 2 + 1]);
                if (MODE == 0) {
                    int b_i = m >> 10, n = m & 1023;
                    int sec = f >> 10;
                    int hh = (f >> 6) & 15, dd = f & 63;
                    size_t idx = ((size_t)(b_i * NHEAD + hh) * NSEQ + n) * HD + dd;
                    __half* dst = (sec == 0) ? g_Qh : (sec == 1) ? g_Kh : g_Vh;
                    *(__half2*)&dst[idx] = __floats2half2_rn(v.x, v.y);
                } else {
                    v.x += bias[f];
                    v.y += bias[f + 1];
                    *(float2*)&C[(size_t)m * DIMC + f] = v;
                }
            }
        }
    }
}

// ============================================================================
// Tensor-core fused causal flash attention with relative position term.
// fp16 single-pass S/R/PV.  R-sweep BEFORE S-sweep (register pressure), R
// scratch in fp16.  SMEM 105.6 KB -> 2 CTAs/SM.
// ============================================================================
#define OFF_Q    0u          // 16KB fp16
#define OFF_K    16384u      // 2 bufs x 8KB
#define OFF_V    32768u      // 2 bufs x 8KB
#define OFF_EHI  49152u      // 4 slots x 8KB
#define OFF_R    81920u      // 8 warps x 1632 halves (3264 B)
#define ATTN_SMEM 108032

__global__ __launch_bounds__(256, 2)
void attn_kernel()
{
    extern __shared__ char smc[];
    const uint32_t sb = smem_u32(smc);
    const int tid  = threadIdx.x;
    const int w    = tid >> 5;
    const int lane = tid & 31;
    const int bq = 7 - (int)blockIdx.x;     // heavy blocks first
    const int bh = blockIdx.y;
    const int n0 = bq * 128;

    const size_t bho = (size_t)bh * NSEQ * HD;
    const __half* Qg = g_Qh + bho;
    const __half* Kg = g_Kh + bho;
    const __half* Vg = g_Vh + bho;

    const int base0 = NSEQ - 128 - n0;      // 64-aligned, >= 0
    const int c0 = base0 >> 6;              // first E chunk index

    // ---- load Q (128 rows fp16, 16KB) ----
#pragma unroll
    for (int t = 0; t < 4; t++) {
        int c = tid + t * 256;
        int row = c >> 3;
        int seg = c & 7;
        cp_async16(sb + OFF_Q + SW128(row * 128 + seg * 16),
                   Qg + (size_t)(n0 + row) * HD + seg * 8);
    }

    auto issueK = [&](int kt) {
        const int km0 = kt * 64;
        const uint32_t kB = OFF_K + (uint32_t)(kt & 1) * 8192u;
#pragma unroll
        for (int t = 0; t < 2; t++) {
            int c = tid + t * 256;
            int row = c >> 3;
            int seg = c & 7;
            cp_async16(sb + kB + SW128(row * 128 + seg * 16),
                       Kg + (size_t)(km0 + row) * HD + seg * 8);
        }
    };
    auto issueV = [&](int kt) {
        const int km0 = kt * 64;
        const uint32_t vB = OFF_V + (uint32_t)(kt & 1) * 8192u;
#pragma unroll
        for (int t = 0; t < 2; t++) {
            int c = tid + t * 256;
            int row = c >> 3;
            int seg = c & 7;
            cp_async16(sb + vB + SW128(row * 128 + seg * 16),
                       Vg + (size_t)(km0 + row) * HD + seg * 8);
        }
    };
    auto issueEchunk = [&](int ci) {
        const int rb = ci << 6;
        const uint32_t slot = ((uint32_t)ci & 3u) * 8192u;
#pragma unroll
        for (int t = 0; t < 2; t++) {
            int c = tid + t * 256;
            int row = c >> 3;
            int seg = c & 7;
            int r = rb + row;
            uint32_t off = OFF_EHI + slot + SW128(row * 128 + seg * 16);
            if (r < NSEQ) {
                cp_async16(sb + off, g_erh + (size_t)r * HD + seg * 8);
            } else {
                *(uint4*)(smc + off) = make_uint4(0u, 0u, 0u, 0u);
            }
        }
    };

    issueK(0); issueV(0);
    issueEchunk(c0); issueEchunk(c0 + 1); issueEchunk(c0 + 2);
    CP_COMMIT();

    float mrow[2] = {-1e30f, -1e30f};
    float lrow[2] = {0.0f, 0.0f};
    float O[8][4];
#pragma unroll
    for (int nt = 0; nt < 8; nt++)
#pragma unroll
        for (int r = 0; r < 4; r++) O[nt][r] = 0.0f;

    const int t0w = 112 - 16 * w;
    const int ktmax = 2 * bq + 1;
    const int eRow0 = base0 + t0w + (lane & 7) + (((lane >> 4) & 1) << 3);

    __half* sRdh = (__half*)(smc + OFF_R) + w * 1632;

    for (int kt = 0; kt <= ktmax; kt++) {
        const int km0 = kt * 64;
        CP_WAIT(0);
        __syncthreads();    // K/E/V(kt) (+Q first iter) visible; prior reads done

        const int eRowK = eRow0 + km0;
        const uint32_t kB   = sb + OFF_K + (uint32_t)(kt & 1) * 8192u;
        const uint32_t eHiB = sb + OFF_EHI;

        // ---- Phase A: R = Qh.Ehi^T, then store fp16 (frees R registers) ----
        {
            float R[10][4];
#pragma unroll
            for (int nt = 0; nt < 10; nt++)
#pragma unroll
                for (int r = 0; r < 4; r++) R[nt][r] = 0.0f;

#pragma unroll
            for (int ks = 0; ks < 4; ks++) {
                const int kb = ks * 32;
                const int arow = 16 * w + (lane & 15);
                uint32_t aH[4];
                LDSM_X4(aH[0], aH[1], aH[2], aH[3],
                        sb + OFF_Q + SW128(arow * 128 + kb + ((lane >> 4) << 4)));
                uint32_t be[5][4];
#pragma unroll
                for (int bt = 0; bt < 5; bt++) {
                    int r = eRowK + bt * 16;
                    uint32_t bd = eHiB + (((uint32_t)(r >> 6) & 3u) * 8192u)
                                + SW128((r & 63) * 128 + kb + (((lane >> 3) & 1) << 4));
                    LDSM_X4(be[bt][0], be[bt][1], be[bt][2], be[bt][3], bd);
                }
#pragma unroll
                for (int nt = 0; nt < 10; nt++) {
                    int bt = nt >> 1, pr = (nt & 1) << 1;
                    MMAH16816(R[nt], aH, be[bt][pr], be[bt][pr + 1]);
                }
            }

            // store diagonal-shifted: (r,c) -> idx 101*r + c + 1 (fp16 scalar)
            int r0 = lane >> 2;
#pragma unroll
            for (int nt = 0; nt < 10; nt++) {
                int cA = nt * 8 + (lane & 3) * 2;
                int i0 = 101 * r0 + cA + 1;
                sRdh[i0]       = __float2half_rn(R[nt][0]);
                sRdh[i0 + 1]   = __float2half_rn(R[nt][1]);
                int i1 = i0 + 808;
                sRdh[i1]       = __float2half_rn(R[nt][2]);
                sRdh[i1 + 1]   = __float2half_rn(R[nt][3]);
            }
        }
        __syncwarp();

        // ---- Phase B: S = Qh.Kh^T ----
        float S[8][4];
#pragma unroll
        for (int nt = 0; nt < 8; nt++)
#pragma unroll
            for (int r = 0; r < 4; r++) S[nt][r] = 0.0f;

#pragma unroll
        for (int ks = 0; ks < 4; ks++) {
            const int kb = ks * 32;
            const int arow = 16 * w + (lane & 15);
            uint32_t aH[4];
            LDSM_X4(aH[0], aH[1], aH[2], aH[3],
                    sb + OFF_Q + SW128(arow * 128 + kb + ((lane >> 4) << 4)));
            uint32_t bk[4][4];
#pragma unroll
            for (int bt = 0; bt < 4; bt++) {
                int row = bt * 16 + (lane & 7) + (((lane >> 4) & 1) << 3);
                uint32_t bd = kB + SW128(row * 128 + kb + (((lane >> 3) & 1) << 4));
                LDSM_X4(bk[bt][0], bk[bt][1], bk[bt][2], bk[bt][3], bd);
            }
#pragma unroll
            for (int nt = 0; nt < 8; nt++) {
                int bt = nt >> 1, pr = (nt & 1) << 1;
                MMAH16816(S[nt], aH, bk[bt][pr], bk[bt][pr + 1]);
            }
        }

        // ---- prefetch next tile (disjoint buffers/slots; no sync needed) ----
        if (kt < ktmax) {
            issueK(kt + 1); issueV(kt + 1); issueEchunk(c0 + kt + 3);
            CP_COMMIT();
        }

        // ---- gather rel (aligned __half2 at il*100 + j0 + 16), scale, mask --
        const bool maskt = (kt >= 2 * bq);
#pragma unroll
        for (int nt = 0; nt < 8; nt++) {
            int j0 = nt * 8 + (lane & 3) * 2;
#pragma unroll
            for (int h = 0; h < 2; h++) {
                int il = (lane >> 2) + 8 * h;
                __half2 hv = *(const __half2*)&sRdh[il * 100 + j0 + 16];
                float2 rv = __half22float2(hv);
                float s0 = (S[nt][2 * h]     + rv.x) * 0.125f;
                float s1 = (S[nt][2 * h + 1] + rv.y) * 0.125f;
                if (maskt) {
                    int ig = n0 + 16 * w + il;
                    int jg = km0 + j0;
                    if (jg > ig)     s0 = -1e30f;
                    if (jg + 1 > ig) s1 = -1e30f;
                }
                S[nt][2 * h]     = s0;
                S[nt][2 * h + 1] = s1;
            }
        }

        // ---- online softmax (rows warp-local; quad = 4 lanes per row) ----
        float alpha[2];
#pragma unroll
        for (int h = 0; h < 2; h++) {
            float v = -1e30f;
#pragma unroll
            for (int nt = 0; nt < 8; nt++)
                v = fmaxf(v, fmaxf(S[nt][2 * h], S[nt][2 * h + 1]));
            v = fmaxf(v, __shfl_xor_sync(0xffffffffu, v, 1));
            v = fmaxf(v, __shfl_xor_sync(0xffffffffu, v, 2));
            float mnew = fmaxf(mrow[h], v);
            alpha[h] = __expf(mrow[h] - mnew);
            mrow[h] = mnew;
        }
        float rsum[2] = {0.0f, 0.0f};
#pragma unroll
        for (int nt = 0; nt < 8; nt++)
#pragma unroll
            for (int h = 0; h < 2; h++) {
                float p0 = __expf(S[nt][2 * h]     - mrow[h]);
                float p1 = __expf(S[nt][2 * h + 1] - mrow[h]);
                S[nt][2 * h] = p0; S[nt][2 * h + 1] = p1;
                rsum[h] += p0 + p1;
            }
#pragma unroll
        for (int h = 0; h < 2; h++) {
            rsum[h] += __shfl_xor_sync(0xffffffffu, rsum[h], 1);
            rsum[h] += __shfl_xor_sync(0xffffffffu, rsum[h], 2);
            lrow[h] = lrow[h] * alpha[h] + rsum[h];
        }
#pragma unroll
        for (int nt = 0; nt < 8; nt++) {
            O[nt][0] *= alpha[0]; O[nt][1] *= alpha[0];
            O[nt][2] *= alpha[1]; O[nt][3] *= alpha[1];
        }

        // ---- pack P fp16 in registers (S-frag layout == A-frag layout) ----
        uint32_t PH[8][2];
#pragma unroll
        for (int nt = 0; nt < 8; nt++) {
#pragma unroll
            for (int pr = 0; pr < 2; pr++) {
                __half2 hh = __floats2half2_rn(S[nt][2 * pr], S[nt][2 * pr + 1]);
                PH[nt][pr] = *(uint32_t*)&hh;
            }
        }

        // ---- O += P.V (single pass, V via ldmatrix.trans) ----
        const uint32_t vB = sb + OFF_V + (uint32_t)(kt & 1) * 8192u;
#pragma unroll
        for (int ks = 0; ks < 4; ks++) {
            uint32_t aP[4] = {PH[2*ks][0], PH[2*ks][1], PH[2*ks+1][0], PH[2*ks+1][1]};
            int row = ks * 16 + (lane & 15);
#pragma unroll
            for (int bt = 0; bt < 4; bt++) {
                uint32_t bd = vB + SW128(row * 128 + bt * 32 + ((lane >> 4) << 4));
                uint32_t r0, r1, r2, r3;
                LDSM_X4T(r0, r1, r2, r3, bd);
                MMAH16816(O[2*bt],     aP, r0, r1);
                MMAH16816(O[2*bt + 1], aP, r2, r3);
            }
        }
    }

    // ---- epilogue: O /= l, fp16 -> g_ath[b][n][h*64+d] ----
    const int b_i = bh >> 4, hhead = bh & 15;
    float inv[2] = {1.0f / lrow[0], 1.0f / lrow[1]};
#pragma unroll
    for (int nt = 0; nt < 8; nt++) {
        int c = hhead * 64 + nt * 8 + (lane & 3) * 2;
#pragma unroll
        for (int h = 0; h < 2; h++) {
            int n = n0 + 16 * w + (lane >> 2) + 8 * h;
            float o0 = O[nt][2 * h] * inv[h];
            float o1 = O[nt][2 * h + 1] * inv[h];
            size_t idx = ((size_t)b_i * NSEQ + n) * DIMC + c;
            *(__half2*)&g_ath[idx] = __floats2half2_rn(o0, o1);
        }
    }
}

// ============================================================================
extern "C" void kernel_launch(void* const* d_in, const int* in_sizes, int n_in,
                              void* d_out, int out_size)
{
    const float* x      = (const float*)d_in[0];
    const float* W_qkv  = (const float*)d_in[1];
    const float* W_proj = (const float*)d_in[2];
    const float* b_proj = (const float*)d_in[3];
    const float* Er     = (const float*)d_in[4];
    float* out = (float*)d_out;

    // 0) fp32 -> fp16 conversions (single launch)
    split_all<<<(NSPLIT4 + 255) / 256, 256>>>(x, W_qkv, W_proj, Er);

    // 1) QKV via fp16 HMMA: M=4096, N=3072 (3-stage x 32KB = 96 KB)
    const int gsmem = 3 * 32768;
    cudaFuncSetAttribute(hmma_gemm<0>,
                         cudaFuncAttributeMaxDynamicSharedMemorySize, gsmem);
    cudaFuncSetAttribute(hmma_gemm<1>,
                         cudaFuncAttributeMaxDynamicSharedMemorySize, gsmem);
    hmma_gemm<0><<<dim3(24, 32), 256, gsmem>>>(nullptr, nullptr);

    // 2) tensor-core fused attention (8 q-blocks x 64 bh), 2 CTAs/SM
    cudaFuncSetAttribute(attn_kernel,
                         cudaFuncAttributeMaxDynamicSharedMemorySize, ATTN_SMEM);
    attn_kernel<<<dim3(8, 64), 256, ATTN_SMEM>>>();

    // 3) proj via fp16 HMMA: M=4096, N=1024, +bias
    hmma_gemm<1><<<dim3(8, 32), 256, gsmem>>>(b_proj, out);
}

// round 17
// speedup vs baseline: 1.5769x; 1.0365x over previous
#include <cuda_runtime.h>
#include <cuda_fp16.h>
#include <cstdint>

#define DIMC  1024
#define NSEQ  1024
#define BATCH 4
#define NHEAD 16
#define HD    64
#define BHTOT (BATCH*NHEAD)

// ---------------- scratch (device globals; no allocation at runtime) ----------
__device__ __half g_Qh[(size_t)BHTOT*NSEQ*HD];
__device__ __half g_Kh[(size_t)BHTOT*NSEQ*HD];
__device__ __half g_Vh[(size_t)BHTOT*NSEQ*HD];

__device__ __half g_xh[(size_t)BATCH*NSEQ*DIMC];
__device__ __half g_wqh[(size_t)3*DIMC*DIMC];
__device__ __half g_wph[(size_t)DIMC*DIMC];
__device__ __half g_ath[(size_t)BATCH*NSEQ*DIMC];
__device__ __half g_erh[(size_t)NSEQ*HD];

// ---------------- helpers ------------------------------------------------------
__device__ __forceinline__ uint32_t smem_u32(const void* p) {
    uint32_t a;
    asm("{ .reg .u64 t; cvta.to.shared.u64 t, %1; cvt.u32.u64 %0, t; }"
        : "=r"(a) : "l"(p));
    return a;
}

__device__ __forceinline__ void cp_async16(uint32_t saddr, const void* gaddr) {
    asm volatile("cp.async.cg.shared.global [%0], [%1], 16;"
                 :: "r"(saddr), "l"(gaddr));
}
#define CP_COMMIT() asm volatile("cp.async.commit_group;" ::: "memory")
#define CP_WAIT(n)  asm volatile("cp.async.wait_group %0;" :: "n"(n) : "memory")

#define LDSM_X4(R0, R1, R2, R3, addr) \
    asm volatile("ldmatrix.sync.aligned.m8n8.x4.shared.b16 {%0,%1,%2,%3}, [%4];" \
                 : "=r"(R0), "=r"(R1), "=r"(R2), "=r"(R3) : "r"(addr))

#define LDSM_X4T(R0, R1, R2, R3, addr) \
    asm volatile("ldmatrix.sync.aligned.m8n8.x4.trans.shared.b16 {%0,%1,%2,%3}, [%4];" \
                 : "=r"(R0), "=r"(R1), "=r"(R2), "=r"(R3) : "r"(addr))

#define MMAH16816(d, a, b0, b1) \
    asm volatile("mma.sync.aligned.m16n8k16.row.col.f32.f16.f16.f32 " \
                 "{%0,%1,%2,%3}, {%4,%5,%6,%7}, {%8,%9}, {%0,%1,%2,%3};" \
                 : "+f"((d)[0]), "+f"((d)[1]), "+f"((d)[2]), "+f"((d)[3]) \
                 : "r"((a)[0]), "r"((a)[1]), "r"((a)[2]), "r"((a)[3]),   \
                   "r"(b0), "r"(b1))

// SW128 (Swizzle<3,4,3>) on byte offsets inside a 1024B-aligned tile
#define SW128(off) (((uint32_t)(off)) ^ ((((uint32_t)(off)) >> 3) & 0x70))

// ============================================================================
// Combined convert fp32 -> fp16: x, W_qkv, W_proj, Er (one launch).
// ============================================================================
#define NX4  1048576
#define NWQ4 786432
#define NWP4 262144
#define NER4 16384
#define NSPLIT4 (NX4 + NWQ4 + NWP4 + NER4)

__global__ void split_all(const float* __restrict__ x, const float* __restrict__ wq,
                          const float* __restrict__ wp, const float* __restrict__ er)
{
    int i = blockIdx.x * blockDim.x + threadIdx.x;
    if (i >= NSPLIT4) return;

    const float* src;
    __half* hi;
    int j;
    if (i < NX4)                    { src = x;  hi = g_xh;  j = i; }
    else if (i < NX4 + NWQ4)        { src = wq; hi = g_wqh; j = i - NX4; }
    else if (i < NX4 + NWQ4 + NWP4) { src = wp; hi = g_wph; j = i - NX4 - NWQ4; }
    else                            { src = er; hi = g_erh; j = i - NX4 - NWQ4 - NWP4; }

    float4 v = ((const float4*)src)[j];
    ((__half2*)hi)[2*j]   = __floats2half2_rn(v.x, v.y);
    ((__half2*)hi)[2*j+1] = __floats2half2_rn(v.z, v.w);
}

// ============================================================================
// HMMA fp16 single-product GEMM: C = A * B^T.   (unchanged from R16)
// ============================================================================
template<int MODE>
__global__ __launch_bounds__(256, 2)
void hmma_gemm(const float* __restrict__ bias, float* __restrict__ C)
{
    extern __shared__ char dynsm[];
    const uint32_t sbase = smem_u32(dynsm);

    const int tid  = threadIdx.x;
    const int wid  = tid >> 5;
    const int lane = tid & 31;
    const int wm = wid & 3;
    const int wn = wid >> 2;
    const int m0 = blockIdx.y * 128;
    const int n0 = blockIdx.x * 128;

    const __half* A = (MODE == 0) ? g_xh : g_ath;
    const __half* B = (MODE == 0) ? g_wqh : g_wph;

    float d[2][8][4];
#pragma unroll
    for (int mt = 0; mt < 2; mt++)
#pragma unroll
        for (int nt = 0; nt < 8; nt++)
#pragma unroll
            for (int r = 0; r < 4; r++) d[mt][nt][r] = 0.0f;

    auto issue_stage = [&](int s) {
        const int kin = s * 64;
        const uint32_t stbase = sbase + (uint32_t)(s % 3) * 32768u;
#pragma unroll
        for (int t = 0; t < 8; t++) {
            int c    = tid + t * 256;
            int part = c >> 10;
            int row  = (c >> 3) & 127;
            int seg  = c & 7;
            const __half* src = part ? B : A;
            int r0 = part ? n0 : m0;
            cp_async16(stbase + (uint32_t)part * 16384u
                           + SW128((uint32_t)(row * 128 + seg * 16)),
                       src + (size_t)(r0 + row) * 1024 + kin + seg * 8);
        }
    };

    issue_stage(0); CP_COMMIT();
    issue_stage(1); CP_COMMIT();

    for (int s = 0; s < 16; s++) {
        if (s == 15) { CP_WAIT(0); } else { CP_WAIT(1); }
        __syncthreads();
        if (s + 2 < 16) { issue_stage(s + 2); CP_COMMIT(); }

        const uint32_t aB = sbase + (uint32_t)(s % 3) * 32768u;
        const uint32_t bB = aB + 16384u;

#pragma unroll
        for (int ks = 0; ks < 4; ks++) {
            const int kb = ks * 32;
            uint32_t a[2][4];
#pragma unroll
            for (int mt = 0; mt < 2; mt++) {
                int row = wm * 32 + mt * 16 + (lane & 15);
                uint32_t off = SW128((uint32_t)(row * 128 + kb + ((lane >> 4) << 4)));
                LDSM_X4(a[mt][0], a[mt][1], a[mt][2], a[mt][3], aB + off);
            }
            uint32_t bb[4][4];
#pragma unroll
            for (int bt = 0; bt < 4; bt++) {
                int row = wn * 64 + bt * 16 + (lane & 7) + (((lane >> 4) & 1) << 3);
                uint32_t bd = bB + SW128((uint32_t)(row * 128 + kb + (((lane >> 3) & 1) << 4)));
                LDSM_X4(bb[bt][0], bb[bt][1], bb[bt][2], bb[bt][3], bd);
            }
#pragma unroll
            for (int mt = 0; mt < 2; mt++)
#pragma unroll
                for (int nt = 0; nt < 8; nt++) {
                    int bt = nt >> 1, pr = (nt & 1) << 1;
                    MMAH16816(d[mt][nt], a[mt], bb[bt][pr], bb[bt][pr + 1]);
                }
        }
    }

    // ---- epilogue ----
#pragma unroll
    for (int mt = 0; mt < 2; mt++) {
        int rbase = m0 + wm * 32 + mt * 16 + (lane >> 2);
#pragma unroll
        for (int nt = 0; nt < 8; nt++) {
            int f = n0 + wn * 64 + nt * 8 + (lane & 3) * 2;
#pragma unroll
            for (int half = 0; half < 2; half++) {
                int m = rbase + half * 8;
                float2 v = make_float2(d[mt][nt][half * 2], d[mt][nt][half * 2 + 1]);
                if (MODE == 0) {
                    int b_i = m >> 10, n = m & 1023;
                    int sec = f >> 10;
                    int hh = (f >> 6) & 15, dd = f & 63;
                    size_t idx = ((size_t)(b_i * NHEAD + hh) * NSEQ + n) * HD + dd;
                    __half* dst = (sec == 0) ? g_Qh : (sec == 1) ? g_Kh : g_Vh;
                    *(__half2*)&dst[idx] = __floats2half2_rn(v.x, v.y);
                } else {
                    v.x += bias[f];
                    v.y += bias[f + 1];
                    *(float2*)&C[(size_t)m * DIMC + f] = v;
                }
            }
        }
    }
}

// ============================================================================
// Tensor-core fused causal flash attention with relative position term.
// Q fragments hoisted to registers (loaded once per q-block).  Prefetch for
// the next tile issued at loop TOP (targets disjoint from all tile-kt reads),
// hidden under the full tile's compute.  LDSM/MMA interleaved per b-tile.
// ============================================================================
#define OFF_Q    0u          // 16KB fp16
#define OFF_K    16384u      // 2 bufs x 8KB
#define OFF_V    32768u      // 2 bufs x 8KB
#define OFF_EHI  49152u      // 4 slots x 8KB
#define OFF_R    81920u      // 8 warps x 1632 halves
#define ATTN_SMEM 108032

__global__ __launch_bounds__(256, 2)
void attn_kernel()
{
    extern __shared__ char smc[];
    const uint32_t sb = smem_u32(smc);
    const int tid  = threadIdx.x;
    const int w    = tid >> 5;
    const int lane = tid & 31;
    const int bq = 7 - (int)blockIdx.x;     // heavy blocks first
    const int bh = blockIdx.y;
    const int n0 = bq * 128;

    const size_t bho = (size_t)bh * NSEQ * HD;
    const __half* Qg = g_Qh + bho;
    const __half* Kg = g_Kh + bho;
    const __half* Vg = g_Vh + bho;

    const int base0 = NSEQ - 128 - n0;      // 64-aligned, >= 0
    const int c0 = base0 >> 6;              // first E chunk index

    // ---- load Q (128 rows fp16, 16KB) ----
#pragma unroll
    for (int t = 0; t < 4; t++) {
        int c = tid + t * 256;
        int row = c >> 3;
        int seg = c & 7;
        cp_async16(sb + OFF_Q + SW128(row * 128 + seg * 16),
                   Qg + (size_t)(n0 + row) * HD + seg * 8);
    }

    auto issueK = [&](int kt) {
        const int km0 = kt * 64;
        const uint32_t kB = OFF_K + (uint32_t)(kt & 1) * 8192u;
#pragma unroll
        for (int t = 0; t < 2; t++) {
            int c = tid + t * 256;
            int row = c >> 3;
            int seg = c & 7;
            cp_async16(sb + kB + SW128(row * 128 + seg * 16),
                       Kg + (size_t)(km0 + row) * HD + seg * 8);
        }
    };
    auto issueV = [&](int kt) {
        const int km0 = kt * 64;
        const uint32_t vB = OFF_V + (uint32_t)(kt & 1) * 8192u;
#pragma unroll
        for (int t = 0; t < 2; t++) {
            int c = tid + t * 256;
            int row = c >> 3;
            int seg = c & 7;
            cp_async16(sb + vB + SW128(row * 128 + seg * 16),
                       Vg + (size_t)(km0 + row) * HD + seg * 8);
        }
    };
    auto issueEchunk = [&](int ci) {
        const int rb = ci << 6;
        const uint32_t slot = ((uint32_t)ci & 3u) * 8192u;
#pragma unroll
        for (int t = 0; t < 2; t++) {
            int c = tid + t * 256;
            int row = c >> 3;
            int seg = c & 7;
            int r = rb + row;
            uint32_t off = OFF_EHI + slot + SW128(row * 128 + seg * 16);
            if (r < NSEQ) {
                cp_async16(sb + off, g_erh + (size_t)r * HD + seg * 8);
            } else {
                *(uint4*)(smc + off) = make_uint4(0u, 0u, 0u, 0u);
            }
        }
    };

    issueK(0); issueV(0);
    issueEchunk(c0); issueEchunk(c0 + 1); issueEchunk(c0 + 2);
    CP_COMMIT();

    float mrow[2] = {-1e30f, -1e30f};
    float lrow[2] = {0.0f, 0.0f};
    float O[8][4];
#pragma unroll
    for (int nt = 0; nt < 8; nt++)
#pragma unroll
        for (int r = 0; r < 4; r++) O[nt][r] = 0.0f;

    const int t0w = 112 - 16 * w;
    const int ktmax = 2 * bq + 1;
    const int eRow0 = base0 + t0w + (lane & 7) + (((lane >> 4) & 1) << 3);

    __half* sRdh = (__half*)(smc + OFF_R) + w * 1632;

    // ---- wait for tile-0 data + Q; hoist Q fragments into registers ----
    CP_WAIT(0);
    __syncthreads();
    uint32_t Qfr[4][4];
    {
        const int arow = 16 * w + (lane & 15);
#pragma unroll
        for (int ks = 0; ks < 4; ks++) {
            LDSM_X4(Qfr[ks][0], Qfr[ks][1], Qfr[ks][2], Qfr[ks][3],
                    sb + OFF_Q + SW128(arow * 128 + ks * 32 + ((lane >> 4) << 4)));
        }
    }

    for (int kt = 0; kt <= ktmax; kt++) {
        const int km0 = kt * 64;
        if (kt > 0) {
            CP_WAIT(0);
            __syncthreads();    // K/E/V(kt) visible; prior-tile reads done
        }
        // ---- prefetch next tile IMMEDIATELY (targets disjoint from tile kt) --
        if (kt < ktmax) {
            issueK(kt + 1); issueV(kt + 1); issueEchunk(c0 + kt + 3);
            CP_COMMIT();
        }

        const int eRowK = eRow0 + km0;
        const uint32_t kB   = sb + OFF_K + (uint32_t)(kt & 1) * 8192u;
        const uint32_t eHiB = sb + OFF_EHI;

        // ---- Phase A: R = Q.E^T (interleaved LDSM/MMA), store fp16 ----
        {
            float R[10][4];
#pragma unroll
            for (int nt = 0; nt < 10; nt++)
#pragma unroll
                for (int r = 0; r < 4; r++) R[nt][r] = 0.0f;

#pragma unroll
            for (int ks = 0; ks < 4; ks++) {
                const int kb = ks * 32;
#pragma unroll
                for (int bt = 0; bt < 5; bt++) {
                    int r = eRowK + bt * 16;
                    uint32_t bd = eHiB + (((uint32_t)(r >> 6) & 3u) * 8192u)
                                + SW128((r & 63) * 128 + kb + (((lane >> 3) & 1) << 4));
                    uint32_t b0, b1, b2, b3;
                    LDSM_X4(b0, b1, b2, b3, bd);
                    MMAH16816(R[2*bt],     Qfr[ks], b0, b1);
                    MMAH16816(R[2*bt + 1], Qfr[ks], b2, b3);
                }
            }

            int r0 = lane >> 2;
#pragma unroll
            for (int nt = 0; nt < 10; nt++) {
                int cA = nt * 8 + (lane & 3) * 2;
                int i0 = 101 * r0 + cA + 1;
                sRdh[i0]     = __float2half_rn(R[nt][0]);
                sRdh[i0 + 1] = __float2half_rn(R[nt][1]);
                int i1 = i0 + 808;
                sRdh[i1]     = __float2half_rn(R[nt][2]);
                sRdh[i1 + 1] = __float2half_rn(R[nt][3]);
            }
        }
        __syncwarp();

        // ---- Phase B: S = Q.K^T (interleaved LDSM/MMA) ----
        float S[8][4];
#pragma unroll
        for (int nt = 0; nt < 8; nt++)
#pragma unroll
            for (int r = 0; r < 4; r++) S[nt][r] = 0.0f;

#pragma unroll
        for (int ks = 0; ks < 4; ks++) {
            const int kb = ks * 32;
#pragma unroll
            for (int bt = 0; bt < 4; bt++) {
                int row = bt * 16 + (lane & 7) + (((lane >> 4) & 1) << 3);
                uint32_t bd = kB + SW128(row * 128 + kb + (((lane >> 3) & 1) << 4));
                uint32_t b0, b1, b2, b3;
                LDSM_X4(b0, b1, b2, b3, bd);
                MMAH16816(S[2*bt],     Qfr[ks], b0, b1);
                MMAH16816(S[2*bt + 1], Qfr[ks], b2, b3);
            }
        }

        // ---- gather rel (aligned __half2 at il*100 + j0 + 16), scale, mask --
        const bool maskt = (kt >= 2 * bq);
#pragma unroll
        for (int nt = 0; nt < 8; nt++) {
            int j0 = nt * 8 + (lane & 3) * 2;
#pragma unroll
            for (int h = 0; h < 2; h++) {
                int il = (lane >> 2) + 8 * h;
                __half2 hv = *(const __half2*)&sRdh[il * 100 + j0 + 16];
                float2 rv = __half22float2(hv);
                float s0 = (S[nt][2 * h]     + rv.x) * 0.125f;
                float s1 = (S[nt][2 * h + 1] + rv.y) * 0.125f;
                if (maskt) {
                    int ig = n0 + 16 * w + il;
                    int jg = km0 + j0;
                    if (jg > ig)     s0 = -1e30f;
                    if (jg + 1 > ig) s1 = -1e30f;
                }
                S[nt][2 * h]     = s0;
                S[nt][2 * h + 1] = s1;
            }
        }

        // ---- online softmax (rows warp-local; quad = 4 lanes per row) ----
        float alpha[2];
#pragma unroll
        for (int h = 0; h < 2; h++) {
            float v = -1e30f;
#pragma unroll
            for (int nt = 0; nt < 8; nt++)
                v = fmaxf(v, fmaxf(S[nt][2 * h], S[nt][2 * h + 1]));
            v = fmaxf(v, __shfl_xor_sync(0xffffffffu, v, 1));
            v = fmaxf(v, __shfl_xor_sync(0xffffffffu, v, 2));
            float mnew = fmaxf(mrow[h], v);
            alpha[h] = __expf(mrow[h] - mnew);
            mrow[h] = mnew;
        }
        float rsum[2] = {0.0f, 0.0f};
#pragma unroll
        for (int nt = 0; nt < 8; nt++)
#pragma unroll
            for (int h = 0; h < 2; h++) {
                float p0 = __expf(S[nt][2 * h]     - mrow[h]);
                float p1 = __expf(S[nt][2 * h + 1] - mrow[h]);
                S[nt][2 * h] = p0; S[nt][2 * h + 1] = p1;
                rsum[h] += p0 + p1;
            }
#pragma unroll
        for (int h = 0; h < 2; h++) {
            rsum[h] += __shfl_xor_sync(0xffffffffu, rsum[h], 1);
            rsum[h] += __shfl_xor_sync(0xffffffffu, rsum[h], 2);
            lrow[h] = lrow[h] * alpha[h] + rsum[h];
        }
#pragma unroll
        for (int nt = 0; nt < 8; nt++) {
            O[nt][0] *= alpha[0]; O[nt][1] *= alpha[0];
            O[nt][2] *= alpha[1]; O[nt][3] *= alpha[1];
        }

        // ---- pack P fp16 in registers (S-frag layout == A-frag layout) ----
        uint32_t PH[8][2];
#pragma unroll
        for (int nt = 0; nt < 8; nt++) {
#pragma unroll
            for (int pr = 0; pr < 2; pr++) {
                __half2 hh = __floats2half2_rn(S[nt][2 * pr], S[nt][2 * pr + 1]);
                PH[nt][pr] = *(uint32_t*)&hh;
            }
        }

        // ---- O += P.V (single pass, V via ldmatrix.trans) ----
        const uint32_t vB = sb + OFF_V + (uint32_t)(kt & 1) * 8192u;
#pragma unroll
        for (int ks = 0; ks < 4; ks++) {
            uint32_t aP[4] = {PH[2*ks][0], PH[2*ks][1], PH[2*ks+1][0], PH[2*ks+1][1]};
            int row = ks * 16 + (lane & 15);
#pragma unroll
            for (int bt = 0; bt < 4; bt++) {
                uint32_t bd = vB + SW128(row * 128 + bt * 32 + ((lane >> 4) << 4));
                uint32_t r0, r1, r2, r3;
                LDSM_X4T(r0, r1, r2, r3, bd);
                MMAH16816(O[2*bt],     aP, r0, r1);
                MMAH16816(O[2*bt + 1], aP, r2, r3);
            }
        }
    }

    // ---- epilogue: O /= l, fp16 -> g_ath[b][n][h*64+d] ----
    const int b_i = bh >> 4, hhead = bh & 15;
    float inv[2] = {1.0f / lrow[0], 1.0f / lrow[1]};
#pragma unroll
    for (int nt = 0; nt < 8; nt++) {
        int c = hhead * 64 + nt * 8 + (lane & 3) * 2;
#pragma unroll
        for (int h = 0; h < 2; h++) {
            int n = n0 + 16 * w + (lane >> 2) + 8 * h;
            float o0 = O[nt][2 * h] * inv[h];
            float o1 = O[nt][2 * h + 1] * inv[h];
            size_t idx = ((size_t)b_i * NSEQ + n) * DIMC + c;
            *(__half2*)&g_ath[idx] = __floats2half2_rn(o0, o1);
        }
    }
}

// ============================================================================
extern "C" void kernel_launch(void* const* d_in, const int* in_sizes, int n_in,
                              void* d_out, int out_size)
{
    const float* x      = (const float*)d_in[0];
    const float* W_qkv  = (const float*)d_in[1];
    const float* W_proj = (const float*)d_in[2];
    const float* b_proj = (const float*)d_in[3];
    const float* Er     = (const float*)d_in[4];
    float* out = (float*)d_out;

    // 0) fp32 -> fp16 conversions (single launch)
    split_all<<<(NSPLIT4 + 255) / 256, 256>>>(x, W_qkv, W_proj, Er);

    // 1) QKV via fp16 HMMA: M=4096, N=3072 (3-stage x 32KB = 96 KB)
    const int gsmem = 3 * 32768;
    cudaFuncSetAttribute(hmma_gemm<0>,
                         cudaFuncAttributeMaxDynamicSharedMemorySize, gsmem);
    cudaFuncSetAttribute(hmma_gemm<1>,
                         cudaFuncAttributeMaxDynamicSharedMemorySize, gsmem);
    hmma_gemm<0><<<dim3(24, 32), 256, gsmem>>>(nullptr, nullptr);

    // 2) tensor-core fused attention (8 q-blocks x 64 bh), 2 CTAs/SM
    cudaFuncSetAttribute(attn_kernel,
                         cudaFuncAttributeMaxDynamicSharedMemorySize, ATTN_SMEM);
    attn_kernel<<<dim3(8, 64), 256, ATTN_SMEM>>>();

    // 3) proj via fp16 HMMA: M=4096, N=1024, +bias
    hmma_gemm<1><<<dim3(8, 32), 256, gsmem>>>(b_proj, out);
}